// round 3
// baseline (speedup 1.0000x reference)
#include <cuda_runtime.h>

// RoiAlign FPN: B=2, N=1000, CROP=7x7, C=256, levels 256/128/64/32/16 (NHWC f32).
// Two-kernel pipeline:
//   k1: one thread per output pixel computes params (feat ptr, 4 corner indices,
//       lx/ly/okf) into __device__ scratch.
//   k2: pure gather+lerp, 256-thread blocks, 4 pixels/block, 1 float4/thread.

#define C4 64                      // 256 channels / 4
#define MAX_PIX (4096 * 49)        // generous upper bound on B*N*49

__device__ float4        g_prmA[MAX_PIX];   // i00,i01,i10,i11 (int bitcast)
__device__ float4        g_prmB[MAX_PIX];   // lx, ly, okf, 0
__device__ const float4* g_fptr[MAX_PIX];   // selected level base pointer

__global__ void roialign_prep(
    const float* __restrict__ boxes,
    const float* __restrict__ f0, const float* __restrict__ f1,
    const float* __restrict__ f2, const float* __restrict__ f3,
    const float* __restrict__ f4,
    const int*   __restrict__ image_shape,
    int N, int npix)
{
    const int pix = blockIdx.x * blockDim.x + threadIdx.x;
    if (pix >= npix) return;
    const int g    = pix % 49;
    const int boxg = pix / 49;
    const int gy   = g / 7;
    const int gx   = g % 7;

    // NOTE: reference unpacks boxes[:,0] as "y1" though setup stacked
    // [x1,y1,x2,y2]; features are square so it's a consistent transpose.
    const float a0 = __ldg(boxes + (size_t)boxg * 4 + 0);
    const float a1 = __ldg(boxes + (size_t)boxg * 4 + 1);
    const float a2 = __ldg(boxes + (size_t)boxg * 4 + 2);
    const float a3 = __ldg(boxes + (size_t)boxg * 4 + 3);

    // lvl = clip(round(log2(sqrt(h*w) / (56/sqrt(area)))), 0, 4)
    const float h     = a3 - a1;
    const float w     = a2 - a0;
    const float area  = (float)(image_shape[0] * image_shape[1]);
    const float denom = 56.0f / sqrtf(area);
    int lvl = (int)rintf(log2f(sqrtf(h * w) / denom));  // round-half-even
    lvl = min(max(lvl, 0), 4);

    const int S = 256 >> lvl;
    const float* feat = (lvl == 0) ? f0 : (lvl == 1) ? f1
                      : (lvl == 2) ? f2 : (lvl == 3) ? f3 : f4;
    const float Hf = (float)(S - 1);

    // Exact reference op order: ys = y1*Hf + gy*((y2-y1)*Hf/6)
    const float ys = a0 * Hf + (float)gy * (((a2 - a0) * Hf) / 6.0f);
    const float xs = a1 * Hf + (float)gx * (((a3 - a1) * Hf) / 6.0f);

    const float y0f = floorf(ys);
    const float x0f = floorf(xs);
    const float ly  = ys - y0f;
    const float lx  = xs - x0f;

    const int y0 = (int)fminf(fmaxf(y0f,        0.0f), Hf);
    const int y1 = (int)fminf(fmaxf(y0f + 1.0f, 0.0f), Hf);
    const int x0 = (int)fminf(fmaxf(x0f,        0.0f), Hf);
    const int x1 = (int)fminf(fmaxf(x0f + 1.0f, 0.0f), Hf);

    const float okf = ((ys >= 0.0f) & (ys <= Hf) &
                       (xs >= 0.0f) & (xs <= Hf)) ? 1.0f : 0.0f;

    const int bS = (boxg / N) * S;
    const int r0 = (bS + y0) * S;
    const int r1 = (bS + y1) * S;
    // flat indices in float4 units (max ~8.4M, int32-safe)
    g_prmA[pix] = make_float4(__int_as_float((r0 + x0) * C4),
                              __int_as_float((r0 + x1) * C4),
                              __int_as_float((r1 + x0) * C4),
                              __int_as_float((r1 + x1) * C4));
    g_prmB[pix] = make_float4(lx, ly, okf, 0.0f);
    g_fptr[pix] = (const float4*)feat;
}

__global__ __launch_bounds__(256) void roialign_gather(
    float* __restrict__ out, int npix)
{
    const int tid = threadIdx.x;
    const int pix = blockIdx.x * 4 + (tid >> 6);
    if (pix >= npix) return;
    const int c = tid & 63;            // float4 channel group 0..63

    const float4* __restrict__ fp = g_fptr[pix];   // broadcast loads
    const float4 qa = g_prmA[pix];
    const float4 qb = g_prmB[pix];

    const int i00 = __float_as_int(qa.x);
    const int i01 = __float_as_int(qa.y);
    const int i10 = __float_as_int(qa.z);
    const int i11 = __float_as_int(qa.w);
    const float lx = qb.x, ly = qb.y, okf = qb.z;

    const float4 v00 = __ldg(fp + i00 + c);
    const float4 v01 = __ldg(fp + i01 + c);
    const float4 v10 = __ldg(fp + i10 + c);
    const float4 v11 = __ldg(fp + i11 + c);

    float4 val;
    {
        float t, btm;
        t = v00.x + lx * (v01.x - v00.x); btm = v10.x + lx * (v11.x - v10.x);
        val.x = (t + ly * (btm - t)) * okf;
        t = v00.y + lx * (v01.y - v00.y); btm = v10.y + lx * (v11.y - v10.y);
        val.y = (t + ly * (btm - t)) * okf;
        t = v00.z + lx * (v01.z - v00.z); btm = v10.z + lx * (v11.z - v10.z);
        val.z = (t + ly * (btm - t)) * okf;
        t = v00.w + lx * (v01.w - v00.w); btm = v10.w + lx * (v11.w - v10.w);
        val.w = (t + ly * (btm - t)) * okf;
    }
    ((float4*)out)[(long)pix * C4 + c] = val;
}

extern "C" void kernel_launch(void* const* d_in, const int* in_sizes, int n_in,
                              void* d_out, int out_size)
{
    const float* boxes = (const float*)d_in[0];
    const float* f0    = (const float*)d_in[1];
    const float* f1    = (const float*)d_in[2];
    const float* f2    = (const float*)d_in[3];
    const float* f3    = (const float*)d_in[4];
    const float* f4    = (const float*)d_in[5];
    const int*   ishp  = (const int*)d_in[6];

    const int BN   = in_sizes[0] / 4;                  // B*N boxes
    const int B    = in_sizes[1] / (256 * 256 * 256);  // feat0 = B*256*256*256
    const int N    = BN / B;
    const int npix = BN * 49;

    roialign_prep<<<(npix + 255) / 256, 256>>>(boxes, f0, f1, f2, f3, f4,
                                               ishp, N, npix);
    roialign_gather<<<(npix + 3) / 4, 256>>>((float*)d_out, npix);
}

// round 4
// speedup vs baseline: 1.1151x; 1.1151x over previous
#include <cuda_runtime.h>

// RoiAlign FPN: B=2, N=1000, CROP=7x7, C=256, levels 256/128/64/32/16 (NHWC f32).
// Fused: one 448-thread block per box. Phase 1 (threads 0..48) precomputes the
// 49 pixel params into smem. Phase 2: 7 pixels/iter x 64 float4 channel groups,
// software-pipelined (prefetch next iter's 4 corner loads before computing the
// current one) so each warp keeps 8 LDG.128 in flight.

#define C4 64  // 256 channels / 4

__global__ __launch_bounds__(448, 2) void roialign_kernel(
    const float* __restrict__ boxes,
    const float* __restrict__ f0, const float* __restrict__ f1,
    const float* __restrict__ f2, const float* __restrict__ f3,
    const float* __restrict__ f4,
    const int*   __restrict__ image_shape,
    float*       __restrict__ out,
    int N)
{
    __shared__ float4 s_a[49];                 // corner indices (int bitcast)
    __shared__ float4 s_b[49];                 // lx, ly, okf, 0
    __shared__ const float4* s_fp;             // selected level base pointer

    const int boxg = blockIdx.x;
    const int tid  = threadIdx.x;

    // ---------------- Phase 1: per-pixel params (threads 0..48) --------------
    if (tid < 49) {
        // NOTE: reference unpacks boxes[:,0] as "y1" though setup stacked
        // [x1,y1,x2,y2]; features are square so it's a consistent transpose.
        const float a0 = __ldg(boxes + (size_t)boxg * 4 + 0);
        const float a1 = __ldg(boxes + (size_t)boxg * 4 + 1);
        const float a2 = __ldg(boxes + (size_t)boxg * 4 + 2);
        const float a3 = __ldg(boxes + (size_t)boxg * 4 + 3);

        // lvl = clip(round(log2(sqrt(h*w) / (56/sqrt(area)))), 0, 4)
        const float h     = a3 - a1;
        const float w     = a2 - a0;
        const float area  = (float)(image_shape[0] * image_shape[1]);
        const float denom = 56.0f / sqrtf(area);
        int lvl = (int)rintf(log2f(sqrtf(h * w) / denom));  // round-half-even
        lvl = min(max(lvl, 0), 4);

        const int S = 256 >> lvl;
        const float* feat = (lvl == 0) ? f0 : (lvl == 1) ? f1
                          : (lvl == 2) ? f2 : (lvl == 3) ? f3 : f4;
        if (tid == 0) s_fp = (const float4*)feat;

        const float Hf = (float)(S - 1);
        const int gy = tid / 7;
        const int gx = tid % 7;

        // Exact reference op order: ys = y1*Hf + gy*((y2-y1)*Hf/6)
        const float ys = a0 * Hf + (float)gy * (((a2 - a0) * Hf) / 6.0f);
        const float xs = a1 * Hf + (float)gx * (((a3 - a1) * Hf) / 6.0f);

        const float y0f = floorf(ys);
        const float x0f = floorf(xs);
        const float ly  = ys - y0f;
        const float lx  = xs - x0f;

        const int y0 = (int)fminf(fmaxf(y0f,        0.0f), Hf);
        const int y1 = (int)fminf(fmaxf(y0f + 1.0f, 0.0f), Hf);
        const int x0 = (int)fminf(fmaxf(x0f,        0.0f), Hf);
        const int x1 = (int)fminf(fmaxf(x0f + 1.0f, 0.0f), Hf);

        const float okf = ((ys >= 0.0f) & (ys <= Hf) &
                           (xs >= 0.0f) & (xs <= Hf)) ? 1.0f : 0.0f;

        const int bS = (boxg / N) * S;
        const int r0 = (bS + y0) * S;
        const int r1 = (bS + y1) * S;
        // flat indices in float4 units (max ~8.4M, int32-safe)
        s_a[tid] = make_float4(__int_as_float((r0 + x0) * C4),
                               __int_as_float((r0 + x1) * C4),
                               __int_as_float((r1 + x0) * C4),
                               __int_as_float((r1 + x1) * C4));
        s_b[tid] = make_float4(lx, ly, okf, 0.0f);
    }
    __syncthreads();

    // ---------------- Phase 2: pipelined gather + lerp -----------------------
    const float4* __restrict__ fp = s_fp;
    const int c    = tid & 63;        // float4 channel group 0..63
    const int psub = tid >> 6;        // pixel sub-slot 0..6
    float4* __restrict__ out4 = (float4*)out + (long)boxg * 49 * C4 + c;

    // Prologue: issue loads for pixel group 0
    int p = psub;
    float4 qa = s_a[p];
    float4 qb = s_b[p];
    float4 v00 = __ldg(fp + __float_as_int(qa.x) + c);
    float4 v01 = __ldg(fp + __float_as_int(qa.y) + c);
    float4 v10 = __ldg(fp + __float_as_int(qa.z) + c);
    float4 v11 = __ldg(fp + __float_as_int(qa.w) + c);

    #pragma unroll
    for (int it = 0; it < 7; ++it) {
        float4 nqa, nqb, n00, n01, n10, n11;
        if (it < 6) {                 // prefetch next pixel group's corners
            const int np = p + 7;
            nqa = s_a[np];
            nqb = s_b[np];
            n00 = __ldg(fp + __float_as_int(nqa.x) + c);
            n01 = __ldg(fp + __float_as_int(nqa.y) + c);
            n10 = __ldg(fp + __float_as_int(nqa.z) + c);
            n11 = __ldg(fp + __float_as_int(nqa.w) + c);
        }

        const float lx = qb.x, ly = qb.y, okf = qb.z;
        float4 val;
        {
            float t, btm;
            t = v00.x + lx * (v01.x - v00.x); btm = v10.x + lx * (v11.x - v10.x);
            val.x = (t + ly * (btm - t)) * okf;
            t = v00.y + lx * (v01.y - v00.y); btm = v10.y + lx * (v11.y - v10.y);
            val.y = (t + ly * (btm - t)) * okf;
            t = v00.z + lx * (v01.z - v00.z); btm = v10.z + lx * (v11.z - v10.z);
            val.z = (t + ly * (btm - t)) * okf;
            t = v00.w + lx * (v01.w - v00.w); btm = v10.w + lx * (v11.w - v10.w);
            val.w = (t + ly * (btm - t)) * okf;
        }
        out4[p * C4] = val;

        p += 7;
        qa = nqa; qb = nqb;
        v00 = n00; v01 = n01; v10 = n10; v11 = n11;
    }
}

extern "C" void kernel_launch(void* const* d_in, const int* in_sizes, int n_in,
                              void* d_out, int out_size)
{
    const float* boxes = (const float*)d_in[0];
    const float* f0    = (const float*)d_in[1];
    const float* f1    = (const float*)d_in[2];
    const float* f2    = (const float*)d_in[3];
    const float* f3    = (const float*)d_in[4];
    const float* f4    = (const float*)d_in[5];
    const int*   ishp  = (const int*)d_in[6];

    const int BN = in_sizes[0] / 4;                    // B*N boxes
    const int B  = in_sizes[1] / (256 * 256 * 256);    // feat0 = B*256*256*256
    const int N  = BN / B;

    roialign_kernel<<<BN, 448>>>(boxes, f0, f1, f2, f3, f4, ishp,
                                 (float*)d_out, N);
}